// round 1
// baseline (speedup 1.0000x reference)
#include <cuda_runtime.h>

#define VCAP 10240

__device__ float    g_newv[VCAP*3];
__device__ float    g_vni [VCAP*3];
__device__ float    g_vnn [VCAP*3];
__device__ float    g_Lv  [VCAP*3];
__device__ float    g_rs  [VCAP];
__device__ unsigned g_minA[VCAP];
__device__ unsigned g_minB[VCAP];
__device__ unsigned g_minS[VCAP];
__device__ double   g_acc [12];

typedef unsigned long long ull;

__device__ __forceinline__ ull pack2(float lo, float hi){
  ull r; asm("mov.b64 %0, {%1, %2};" : "=l"(r) : "f"(lo), "f"(hi)); return r;
}
__device__ __forceinline__ void unpack2(ull v, float& lo, float& hi){
  asm("mov.b64 {%0, %1}, %2;" : "=f"(lo), "=f"(hi) : "l"(v));
}
__device__ __forceinline__ ull add2(ull a, ull b){ ull r; asm("add.rn.f32x2 %0, %1, %2;" : "=l"(r) : "l"(a), "l"(b)); return r; }
__device__ __forceinline__ ull mul2(ull a, ull b){ ull r; asm("mul.rn.f32x2 %0, %1, %2;" : "=l"(r) : "l"(a), "l"(b)); return r; }
__device__ __forceinline__ ull fma2(ull a, ull b, ull c){ ull r; asm("fma.rn.f32x2 %0, %1, %2, %3;" : "=l"(r) : "l"(a), "l"(b), "l"(c)); return r; }

struct F3 { float x, y, z; };
__device__ __forceinline__ F3 ld3(const float* p, int i){ F3 r; r.x = p[3*i]; r.y = p[3*i+1]; r.z = p[3*i+2]; return r; }
__device__ __forceinline__ F3 sub3(F3 a, F3 b){ F3 r; r.x=a.x-b.x; r.y=a.y-b.y; r.z=a.z-b.z; return r; }
__device__ __forceinline__ F3 cross3(F3 a, F3 b){
  F3 r; r.x = a.y*b.z - a.z*b.y; r.y = a.z*b.x - a.x*b.z; r.z = a.x*b.y - a.y*b.x; return r;
}
__device__ __forceinline__ float dot3(F3 a, F3 b){ return a.x*b.x + a.y*b.y + a.z*b.z; }
__device__ __forceinline__ float len3(F3 a){ return sqrtf(dot3(a,a)); }

__device__ __forceinline__ void waccum(int slot, float v){
  #pragma unroll
  for (int o = 16; o; o >>= 1) v += __shfl_xor_sync(0xffffffffu, v, o);
  if ((threadIdx.x & 31) == 0) atomicAdd(&g_acc[slot], (double)v);
}

// ---------------------------------------------------------------------------
// init: new_v = verts + deform; zero scratch; mins = +inf; acc = 0
// ---------------------------------------------------------------------------
__global__ void k_init(const float* __restrict__ verts, const float* __restrict__ deform, int V){
  int i = blockIdx.x * blockDim.x + threadIdx.x;
  if (i < V*3){
    g_newv[i] = verts[i] + deform[i];
    g_vni[i] = 0.f; g_vnn[i] = 0.f; g_Lv[i] = 0.f;
  }
  if (i < V){
    g_rs[i] = 0.f;
    g_minA[i] = 0x7f800000u; g_minB[i] = 0x7f800000u; g_minS[i] = 0x7f800000u;
  }
  if (i < 12) g_acc[i] = 0.0;
}

// ---------------------------------------------------------------------------
// per-face: normals scatter (verts & new_v), edge loss, smooth loss, cot laplacian scatter
// acc[0] = edge loss sum, acc[1] = smooth sum
// ---------------------------------------------------------------------------
__global__ void k_face(const float* __restrict__ verts, const float* __restrict__ deform,
                       const int* __restrict__ faces, int F){
  int f = blockIdx.x * blockDim.x + threadIdx.x;
  float el = 0.f, sm = 0.f;
  if (f < F){
    int i0 = faces[3*f], i1 = faces[3*f+1], i2 = faces[3*f+2];

    // initial-verts face normal
    F3 v0 = ld3(verts, i0), v1 = ld3(verts, i1), v2 = ld3(verts, i2);
    F3 n = cross3(sub3(v1, v0), sub3(v2, v0));
    atomicAdd(&g_vni[3*i0+0], n.x); atomicAdd(&g_vni[3*i0+1], n.y); atomicAdd(&g_vni[3*i0+2], n.z);
    atomicAdd(&g_vni[3*i1+0], n.x); atomicAdd(&g_vni[3*i1+1], n.y); atomicAdd(&g_vni[3*i1+2], n.z);
    atomicAdd(&g_vni[3*i2+0], n.x); atomicAdd(&g_vni[3*i2+1], n.y); atomicAdd(&g_vni[3*i2+2], n.z);

    // new-verts face normal
    F3 w0 = ld3(g_newv, i0), w1 = ld3(g_newv, i1), w2 = ld3(g_newv, i2);
    F3 m = cross3(sub3(w1, w0), sub3(w2, w0));
    atomicAdd(&g_vnn[3*i0+0], m.x); atomicAdd(&g_vnn[3*i0+1], m.y); atomicAdd(&g_vnn[3*i0+2], m.z);
    atomicAdd(&g_vnn[3*i1+0], m.x); atomicAdd(&g_vnn[3*i1+1], m.y); atomicAdd(&g_vnn[3*i1+2], m.z);
    atomicAdd(&g_vnn[3*i2+0], m.x); atomicAdd(&g_vnn[3*i2+1], m.y); atomicAdd(&g_vnn[3*i2+2], m.z);

    // edge-length regularity on new_v
    float e0 = len3(sub3(w0, w1));
    float e1 = len3(sub3(w1, w2));
    float e2 = len3(sub3(w2, w0));
    el = (e0-e1)*(e0-e1) + (e1-e2)*(e1-e2) + (e2-e0)*(e2-e0);

    // smooth: offsets are exactly deform
    F3 d0 = ld3(deform, i0), d1 = ld3(deform, i1), d2 = ld3(deform, i2);
    sm  = fabsf(d0.x-d1.x) + fabsf(d0.y-d1.y) + fabsf(d0.z-d1.z);
    sm += fabsf(d1.x-d2.x) + fabsf(d1.y-d2.y) + fabsf(d1.z-d2.z);
    sm += fabsf(d2.x-d0.x) + fabsf(d2.y-d0.y) + fabsf(d2.z-d0.z);

    // cotangent laplacian scatter (on new_v)
    float a = e1, b = e2, c = e0;                  // a=|w1-w2|, b=|w0-w2|, c=|w0-w1|
    float s = 0.5f * (a + b + c);
    float ar2 = s * (s-a) * (s-b) * (s-c);
    float area = sqrtf(fmaxf(ar2, 1e-12f));
    float inv4a = 0.25f / area;
    float a2 = a*a, b2 = b*b, c2 = c*c;
    float c0 = (b2 + c2 - a2) * inv4a;            // edge (i1,i2)
    float c1 = (a2 + c2 - b2) * inv4a;            // edge (i2,i0)
    float c2w = (a2 + b2 - c2) * inv4a;           // edge (i0,i1)

    // Lv[ii] += w*v[jj]; Lv[jj] += w*v[ii]; rs[ii]+=w; rs[jj]+=w
    atomicAdd(&g_Lv[3*i1+0], c0*w2.x); atomicAdd(&g_Lv[3*i1+1], c0*w2.y); atomicAdd(&g_Lv[3*i1+2], c0*w2.z);
    atomicAdd(&g_Lv[3*i2+0], c0*w1.x); atomicAdd(&g_Lv[3*i2+1], c0*w1.y); atomicAdd(&g_Lv[3*i2+2], c0*w1.z);
    atomicAdd(&g_rs[i1], c0); atomicAdd(&g_rs[i2], c0);

    atomicAdd(&g_Lv[3*i2+0], c1*w0.x); atomicAdd(&g_Lv[3*i2+1], c1*w0.y); atomicAdd(&g_Lv[3*i2+2], c1*w0.z);
    atomicAdd(&g_Lv[3*i0+0], c1*w2.x); atomicAdd(&g_Lv[3*i0+1], c1*w2.y); atomicAdd(&g_Lv[3*i0+2], c1*w2.z);
    atomicAdd(&g_rs[i2], c1); atomicAdd(&g_rs[i0], c1);

    atomicAdd(&g_Lv[3*i0+0], c2w*w1.x); atomicAdd(&g_Lv[3*i0+1], c2w*w1.y); atomicAdd(&g_Lv[3*i0+2], c2w*w1.z);
    atomicAdd(&g_Lv[3*i1+0], c2w*w0.x); atomicAdd(&g_Lv[3*i1+1], c2w*w0.y); atomicAdd(&g_Lv[3*i1+2], c2w*w0.z);
    atomicAdd(&g_rs[i0], c2w); atomicAdd(&g_rs[i1], c2w);
  }
  waccum(0, el);
  waccum(1, sm);
}

// ---------------------------------------------------------------------------
// per-interior-edge normal consistency (on new_v). acc[2]
// ---------------------------------------------------------------------------
__global__ void k_edge(const int* __restrict__ ev, const int* __restrict__ eo, int E){
  int e = blockIdx.x * blockDim.x + threadIdx.x;
  float val = 0.f;
  if (e < E){
    int a = ev[2*e], b = ev[2*e+1], o0 = eo[2*e], o1 = eo[2*e+1];
    F3 va = ld3(g_newv, a), vb = ld3(g_newv, b);
    F3 p0 = ld3(g_newv, o0), p1 = ld3(g_newv, o1);
    F3 ed = sub3(vb, va);
    F3 n0 = cross3(ed, sub3(p0, va));
    F3 n1 = cross3(ed, sub3(p1, va));
    n1.x = -n1.x; n1.y = -n1.y; n1.z = -n1.z;
    float dt = dot3(n0, n1);
    float dn = sqrtf(dot3(n0,n0)) * sqrtf(dot3(n1,n1));
    float cosv = dt / fmaxf(dn, 1e-8f);
    val = 1.0f - cosv;
  }
  waccum(2, val);
}

// ---------------------------------------------------------------------------
// per-vertex: normalize normals, consistency (acc[4]), penetration (acc[5]),
// laplacian norm (acc[3])
// ---------------------------------------------------------------------------
__global__ void k_vert(const float* __restrict__ deform, int V){
  int i = blockIdx.x * blockDim.x + threadIdx.x;
  float cons = 0.f, pen = 0.f, lap = 0.f;
  if (i < V){
    F3 a = ld3(g_vni, i);
    float la = sqrtf(dot3(a,a));
    float ia = 1.0f / fmaxf(la, 1e-6f);
    F3 ni; ni.x = a.x*ia; ni.y = a.y*ia; ni.z = a.z*ia;

    F3 b = ld3(g_vnn, i);
    float lb = sqrtf(dot3(b,b));
    float ib = 1.0f / fmaxf(lb, 1e-6f);
    F3 nn; nn.x = b.x*ib; nn.y = b.y*ib; nn.z = b.z*ib;

    float dx = nn.x-ni.x, dy = nn.y-ni.y, dz = nn.z-ni.z;
    cons = dx*dx + dy*dy + dz*dz;

    F3 df = ld3(deform, i);
    float p = dot3(df, ni);
    pen = fmaxf(-p, 0.f);                 // |min(p,0)|

    float r = g_rs[i];
    float inv = (r > 0.f) ? (1.0f / r) : 0.f;
    F3 lv = ld3(g_Lv, i);
    F3 nv = ld3(g_newv, i);
    float ex = lv.x*inv - nv.x, ey = lv.y*inv - nv.y, ez = lv.z*inv - nv.z;
    lap = sqrtf(ex*ex + ey*ey + ez*ez);
  }
  waccum(4, cons);
  waccum(5, pen);
  waccum(3, lap);
}

// ---------------------------------------------------------------------------
// chamfer pass, f32x2 packed, 4 x-points/thread, Y chunked across blockIdx.y.
// MODE 0: X=new_v, Y=trg   -> g_minA  (x -> nearest trg)
// MODE 1: X=trg,   Y=new_v -> g_minB  (trg -> nearest x)
// MODE 2: X=new_v, Y=flip(new_v) -> g_minS  (symmetric, doubled at finalize)
// ---------------------------------------------------------------------------
#define NCH 28

template<int MODE>
__global__ void __launch_bounds__(256) k_chamfer(const float* __restrict__ trg, int n, int chunk){
  __shared__ ull sY[384*3];
  const float* __restrict__ Y = (MODE == 0) ? trg : g_newv;
  int y0 = blockIdx.y * chunk;
  int y1 = y0 + chunk; if (y1 > n) y1 = n;
  int cnt = y1 - y0;

  for (int j = threadIdx.x; j < cnt; j += 256){
    const float* yp = Y + (size_t)(y0 + j) * 3;
    float yx = yp[0], yy = yp[1], yz = yp[2];
    if (MODE == 2) yx = -yx;                 // flip = (-1,1,1) on x
    sY[j*3+0] = pack2(-yx, -yx);             // store negated, broadcast into both lanes
    sY[j*3+1] = pack2(-yy, -yy);
    sY[j*3+2] = pack2(-yz, -yz);
  }
  __syncthreads();

  const float* __restrict__ X = (MODE == 1) ? trg : g_newv;
  int base = blockIdx.x * 1024 + threadIdx.x;
  int xi0 = base, xi1 = base + 256, xi2 = base + 512, xi3 = base + 768;
  int c0 = min(xi0, n-1), c1 = min(xi1, n-1), c2 = min(xi2, n-1), c3 = min(xi3, n-1);
  F3 x0 = ld3(X, c0), x1 = ld3(X, c1), x2 = ld3(X, c2), x3 = ld3(X, c3);

  ull Xx0 = pack2(x0.x, x1.x), Xy0 = pack2(x0.y, x1.y), Xz0 = pack2(x0.z, x1.z);
  ull Xx1 = pack2(x2.x, x3.x), Xy1 = pack2(x2.y, x3.y), Xz1 = pack2(x2.z, x3.z);

  float m0 = __int_as_float(0x7f800000), m1 = m0, m2 = m0, m3 = m0;

  #pragma unroll 2
  for (int j = 0; j < cnt; j++){
    ull ax = sY[j*3+0], ay = sY[j*3+1], az = sY[j*3+2];
    float lo, hi;
    ull dx = add2(Xx0, ax), dy = add2(Xy0, ay), dz = add2(Xz0, az);
    ull d  = mul2(dx, dx); d = fma2(dy, dy, d); d = fma2(dz, dz, d);
    unpack2(d, lo, hi);
    m0 = fminf(m0, lo); m1 = fminf(m1, hi);
    dx = add2(Xx1, ax); dy = add2(Xy1, ay); dz = add2(Xz1, az);
    d  = mul2(dx, dx); d = fma2(dy, dy, d); d = fma2(dz, dz, d);
    unpack2(d, lo, hi);
    m2 = fminf(m2, lo); m3 = fminf(m3, hi);
  }

  unsigned* gm = (MODE == 0) ? g_minA : (MODE == 1) ? g_minB : g_minS;
  if (xi0 < n) atomicMin(&gm[xi0], __float_as_uint(m0));
  if (xi1 < n) atomicMin(&gm[xi1], __float_as_uint(m1));
  if (xi2 < n) atomicMin(&gm[xi2], __float_as_uint(m2));
  if (xi3 < n) atomicMin(&gm[xi3], __float_as_uint(m3));
}

// ---------------------------------------------------------------------------
// reduce chamfer mins. acc[6]=A, acc[7]=B, acc[8]=S
// ---------------------------------------------------------------------------
__global__ void k_minred(int V){
  int i = blockIdx.x * blockDim.x + threadIdx.x;
  float a = 0.f, b = 0.f, s = 0.f;
  if (i < V){
    a = __uint_as_float(g_minA[i]);
    b = __uint_as_float(g_minB[i]);
    s = __uint_as_float(g_minS[i]);
  }
  waccum(6, a);
  waccum(7, b);
  waccum(8, s);
}

// ---------------------------------------------------------------------------
// final combine
// ---------------------------------------------------------------------------
__global__ void k_final(float* out, int V, int F, int E){
  double dV = (double)V, dF = (double)F, dE = (double)E;
  double loss = (g_acc[6] + g_acc[7]) / dV;        // chamfer (both directions)
  loss += 0.1 * (g_acc[0] / dF);                   // edge
  loss += 0.1 * (g_acc[2] / dE);                   // normal consistency
  loss += 0.1 * (g_acc[1] / (3.0 * dF));           // smooth
  loss += 0.1 * (g_acc[3] / dV);                   // laplacian
  loss += 0.1 * (g_acc[4] / (3.0 * dV));           // consistency
  loss += 0.1 * (2.0 * g_acc[8] / dV);             // symmetry (matrix symmetric => 2x rowmin)
  loss += 0.1 * (g_acc[5] / dV);                   // penetration
  out[0] = (float)loss;
}

extern "C" void kernel_launch(void* const* d_in, const int* in_sizes, int n_in,
                              void* d_out, int out_size){
  const float* verts  = (const float*)d_in[0];
  const float* deform = (const float*)d_in[1];
  const float* trg    = (const float*)d_in[2];
  const int*   faces  = (const int*)d_in[3];
  const int*   ev     = (const int*)d_in[4];
  const int*   eo     = (const int*)d_in[5];
  int V = in_sizes[0] / 3;
  int F = in_sizes[3] / 3;
  int E = in_sizes[4] / 2;

  k_init<<<(V*3 + 255)/256, 256>>>(verts, deform, V);
  k_face<<<(F + 255)/256, 256>>>(verts, deform, faces, F);
  k_edge<<<(E + 255)/256, 256>>>(ev, eo, E);
  k_vert<<<(V + 255)/256, 256>>>(deform, V);

  int chunk = (V + NCH - 1) / NCH;
  dim3 grid((V + 1023)/1024, NCH);
  k_chamfer<0><<<grid, 256>>>(trg, V, chunk);
  k_chamfer<1><<<grid, 256>>>(trg, V, chunk);
  k_chamfer<2><<<grid, 256>>>(trg, V, chunk);

  k_minred<<<(V + 255)/256, 256>>>(V);
  k_final<<<1, 1>>>((float*)d_out, V, F, E);
}

// round 2
// speedup vs baseline: 1.3716x; 1.3716x over previous
#include <cuda_runtime.h>

#define VCAP 10240
#define NCH  64
#define CHMAX 160

__device__ float    g_vni [VCAP*3];
__device__ float    g_vnn [VCAP*3];
__device__ float    g_Lv  [VCAP*3];
__device__ float    g_rs  [VCAP];
__device__ float    g_part[3*NCH*VCAP];
__device__ double   g_acc [12];
__device__ unsigned g_done;

typedef unsigned long long ull;

__device__ __forceinline__ ull pack2(float lo, float hi){
  ull r; asm("mov.b64 %0, {%1, %2};" : "=l"(r) : "f"(lo), "f"(hi)); return r;
}
__device__ __forceinline__ void unpack2(ull v, float& lo, float& hi){
  asm("mov.b64 {%0, %1}, %2;" : "=f"(lo), "=f"(hi) : "l"(v));
}
__device__ __forceinline__ ull fma2(ull a, ull b, ull c){
  ull r; asm("fma.rn.f32x2 %0, %1, %2, %3;" : "=l"(r) : "l"(a), "l"(b), "l"(c)); return r;
}

struct F3 { float x, y, z; };
__device__ __forceinline__ F3 ld3(const float* p, int i){ F3 r; r.x=p[3*i]; r.y=p[3*i+1]; r.z=p[3*i+2]; return r; }
__device__ __forceinline__ F3 sub3(F3 a, F3 b){ F3 r; r.x=a.x-b.x; r.y=a.y-b.y; r.z=a.z-b.z; return r; }
__device__ __forceinline__ F3 cross3(F3 a, F3 b){
  F3 r; r.x=a.y*b.z-a.z*b.y; r.y=a.z*b.x-a.x*b.z; r.z=a.x*b.y-a.y*b.x; return r;
}
__device__ __forceinline__ float dot3(F3 a, F3 b){ return a.x*b.x + a.y*b.y + a.z*b.z; }
__device__ __forceinline__ float len3(F3 a){ return sqrtf(dot3(a,a)); }
__device__ __forceinline__ F3 newv(const float* v, const float* d, int i){
  F3 r; r.x=v[3*i]+d[3*i]; r.y=v[3*i+1]+d[3*i+1]; r.z=v[3*i+2]+d[3*i+2]; return r;
}

__device__ __forceinline__ void waccum(int slot, float v){
  #pragma unroll
  for (int o = 16; o; o >>= 1) v += __shfl_xor_sync(0xffffffffu, v, o);
  if ((threadIdx.x & 31) == 0) atomicAdd(&g_acc[slot], (double)v);
}

// ---------------------------------------------------------------------------
// k_main: one launch. Blocks [0,FB): face+edge work. Blocks [FB, FB+XB*3*NCH):
// chamfer tiles (xblk, mode, chunk). Partial mins (dot form, without |x|^2)
// go to g_part via plain stores — no init needed.
//   mode 0: X=new_v, Y=trg        mode 1: X=trg, Y=new_v
//   mode 2: X=new_v, Y=flip(new_v)   (symmetric matrix -> 2x rowmin at combine)
// Invariant: g_vni/g_vnn/g_Lv/g_rs zero and g_acc zero at entry (initial static
// zero; k_vert resets them after use, so every graph replay sees the invariant).
// ---------------------------------------------------------------------------
__global__ void __launch_bounds__(256) k_main(
    const float* __restrict__ verts, const float* __restrict__ deform,
    const float* __restrict__ trg,   const int* __restrict__ faces,
    const int* __restrict__ ev,      const int* __restrict__ eo,
    int V, int F, int E, int FB, int XB, int CH)
{
  __shared__ __align__(16) ull sY[CHMAX*4];
  int bid = blockIdx.x;

  if (bid < FB){
    // ---------------- face + edge blocks ----------------
    int f = bid*256 + threadIdx.x;
    float el = 0.f, sm = 0.f, nc = 0.f;
    if (f < F){
      int i0 = faces[3*f], i1 = faces[3*f+1], i2 = faces[3*f+2];

      F3 v0 = ld3(verts, i0), v1 = ld3(verts, i1), v2 = ld3(verts, i2);
      F3 n = cross3(sub3(v1, v0), sub3(v2, v0));
      atomicAdd(&g_vni[3*i0+0], n.x); atomicAdd(&g_vni[3*i0+1], n.y); atomicAdd(&g_vni[3*i0+2], n.z);
      atomicAdd(&g_vni[3*i1+0], n.x); atomicAdd(&g_vni[3*i1+1], n.y); atomicAdd(&g_vni[3*i1+2], n.z);
      atomicAdd(&g_vni[3*i2+0], n.x); atomicAdd(&g_vni[3*i2+1], n.y); atomicAdd(&g_vni[3*i2+2], n.z);

      F3 d0 = ld3(deform, i0), d1 = ld3(deform, i1), d2 = ld3(deform, i2);
      F3 w0, w1, w2;
      w0.x=v0.x+d0.x; w0.y=v0.y+d0.y; w0.z=v0.z+d0.z;
      w1.x=v1.x+d1.x; w1.y=v1.y+d1.y; w1.z=v1.z+d1.z;
      w2.x=v2.x+d2.x; w2.y=v2.y+d2.y; w2.z=v2.z+d2.z;
      F3 m = cross3(sub3(w1, w0), sub3(w2, w0));
      atomicAdd(&g_vnn[3*i0+0], m.x); atomicAdd(&g_vnn[3*i0+1], m.y); atomicAdd(&g_vnn[3*i0+2], m.z);
      atomicAdd(&g_vnn[3*i1+0], m.x); atomicAdd(&g_vnn[3*i1+1], m.y); atomicAdd(&g_vnn[3*i1+2], m.z);
      atomicAdd(&g_vnn[3*i2+0], m.x); atomicAdd(&g_vnn[3*i2+1], m.y); atomicAdd(&g_vnn[3*i2+2], m.z);

      float e0 = len3(sub3(w0, w1));
      float e1 = len3(sub3(w1, w2));
      float e2 = len3(sub3(w2, w0));
      el = (e0-e1)*(e0-e1) + (e1-e2)*(e1-e2) + (e2-e0)*(e2-e0);

      sm  = fabsf(d0.x-d1.x) + fabsf(d0.y-d1.y) + fabsf(d0.z-d1.z);
      sm += fabsf(d1.x-d2.x) + fabsf(d1.y-d2.y) + fabsf(d1.z-d2.z);
      sm += fabsf(d2.x-d0.x) + fabsf(d2.y-d0.y) + fabsf(d2.z-d0.z);

      float a = e1, b = e2, c = e0;
      float s = 0.5f * (a + b + c);
      float area = sqrtf(fmaxf(s*(s-a)*(s-b)*(s-c), 1e-12f));
      float inv4a = 0.25f / area;
      float a2=a*a, b2=b*b, c2=c*c;
      float c0w = (b2 + c2 - a2) * inv4a;   // edge (i1,i2)
      float c1w = (a2 + c2 - b2) * inv4a;   // edge (i2,i0)
      float c2w = (a2 + b2 - c2) * inv4a;   // edge (i0,i1)

      atomicAdd(&g_Lv[3*i1+0], c0w*w2.x); atomicAdd(&g_Lv[3*i1+1], c0w*w2.y); atomicAdd(&g_Lv[3*i1+2], c0w*w2.z);
      atomicAdd(&g_Lv[3*i2+0], c0w*w1.x); atomicAdd(&g_Lv[3*i2+1], c0w*w1.y); atomicAdd(&g_Lv[3*i2+2], c0w*w1.z);
      atomicAdd(&g_rs[i1], c0w); atomicAdd(&g_rs[i2], c0w);

      atomicAdd(&g_Lv[3*i2+0], c1w*w0.x); atomicAdd(&g_Lv[3*i2+1], c1w*w0.y); atomicAdd(&g_Lv[3*i2+2], c1w*w0.z);
      atomicAdd(&g_Lv[3*i0+0], c1w*w2.x); atomicAdd(&g_Lv[3*i0+1], c1w*w2.y); atomicAdd(&g_Lv[3*i0+2], c1w*w2.z);
      atomicAdd(&g_rs[i2], c1w); atomicAdd(&g_rs[i0], c1w);

      atomicAdd(&g_Lv[3*i0+0], c2w*w1.x); atomicAdd(&g_Lv[3*i0+1], c2w*w1.y); atomicAdd(&g_Lv[3*i0+2], c2w*w1.z);
      atomicAdd(&g_Lv[3*i1+0], c2w*w0.x); atomicAdd(&g_Lv[3*i1+1], c2w*w0.y); atomicAdd(&g_Lv[3*i1+2], c2w*w0.z);
      atomicAdd(&g_rs[i0], c2w); atomicAdd(&g_rs[i1], c2w);
    }
    if (f < E){
      int a = ev[2*f], b = ev[2*f+1], o0 = eo[2*f], o1 = eo[2*f+1];
      F3 va = newv(verts, deform, a),  vb = newv(verts, deform, b);
      F3 p0 = newv(verts, deform, o0), p1 = newv(verts, deform, o1);
      F3 edg = sub3(vb, va);
      F3 n0 = cross3(edg, sub3(p0, va));
      F3 n1 = cross3(edg, sub3(p1, va));
      n1.x = -n1.x; n1.y = -n1.y; n1.z = -n1.z;
      float dt = dot3(n0, n1);
      float dn = sqrtf(dot3(n0,n0)) * sqrtf(dot3(n1,n1));
      nc = 1.0f - dt / fmaxf(dn, 1e-8f);
    }
    waccum(0, el);
    waccum(1, sm);
    waccum(2, nc);
    return;
  }

  // ---------------- chamfer blocks ----------------
  int cid   = bid - FB;
  int xblk  = cid % XB;
  int rest  = cid / XB;
  int mode  = rest % 3;
  int chunk = rest / 3;

  int y0  = chunk * CH;
  int cnt = V - y0; if (cnt > CH) cnt = CH; if (cnt < 0) cnt = 0;

  for (int j = threadIdx.x; j < cnt; j += 256){
    int yi = y0 + j;
    float yx, yy, yz;
    if (mode == 0){
      yx = trg[3*yi]; yy = trg[3*yi+1]; yz = trg[3*yi+2];
    } else {
      yx = verts[3*yi]   + deform[3*yi];
      yy = verts[3*yi+1] + deform[3*yi+1];
      yz = verts[3*yi+2] + deform[3*yi+2];
      if (mode == 2) yx = -yx;
    }
    float q = yx*yx + yy*yy + yz*yz;
    sY[j*4+0] = pack2(-2.f*yx, -2.f*yx);
    sY[j*4+1] = pack2(-2.f*yy, -2.f*yy);
    sY[j*4+2] = pack2(-2.f*yz, -2.f*yz);
    sY[j*4+3] = pack2(q, q);
  }
  __syncthreads();

  int base = xblk*2048 + threadIdx.x;
  float xs[8][3];
  #pragma unroll
  for (int k = 0; k < 8; k++){
    int idx = base + 256*k; if (idx >= V) idx = V-1;
    if (mode == 1){
      xs[k][0] = trg[3*idx]; xs[k][1] = trg[3*idx+1]; xs[k][2] = trg[3*idx+2];
    } else {
      xs[k][0] = verts[3*idx]   + deform[3*idx];
      xs[k][1] = verts[3*idx+1] + deform[3*idx+1];
      xs[k][2] = verts[3*idx+2] + deform[3*idx+2];
    }
  }
  ull Xx[4], Xy[4], Xz[4];
  #pragma unroll
  for (int p = 0; p < 4; p++){
    Xx[p] = pack2(xs[2*p][0], xs[2*p+1][0]);
    Xy[p] = pack2(xs[2*p][1], xs[2*p+1][1]);
    Xz[p] = pack2(xs[2*p][2], xs[2*p+1][2]);
  }
  float m[8];
  #pragma unroll
  for (int k = 0; k < 8; k++) m[k] = __int_as_float(0x7f800000);

  const ulonglong2* sp = (const ulonglong2*)sY;
  #pragma unroll 2
  for (int j = 0; j < cnt; j++){
    ulonglong2 A = sp[2*j];      // (-2yx, -2yy)
    ulonglong2 B = sp[2*j+1];    // (-2yz, |y|^2)
    #pragma unroll
    for (int p = 0; p < 4; p++){
      ull t = fma2(Xx[p], A.x, B.y);
      t = fma2(Xy[p], A.y, t);
      t = fma2(Xz[p], B.x, t);
      float lo, hi; unpack2(t, lo, hi);
      m[2*p]   = fminf(m[2*p],   lo);
      m[2*p+1] = fminf(m[2*p+1], hi);
    }
  }

  float* part = g_part + (size_t)(mode*NCH + chunk) * VCAP;
  #pragma unroll
  for (int k = 0; k < 8; k++){
    int idx = base + 256*k;
    if (idx < V) part[idx] = m[k];
  }
}

// ---------------------------------------------------------------------------
// k_vert: reduce chamfer partials (+|x|^2), vertex-normal consistency,
// penetration, laplacian norm; reset scatter arrays for the next replay;
// last block folds g_acc into the final scalar and resets g_acc.
// ---------------------------------------------------------------------------
__global__ void __launch_bounds__(256) k_vert(
    const float* __restrict__ verts, const float* __restrict__ deform,
    const float* __restrict__ trg, float* __restrict__ out,
    int V, int F, int E)
{
  int i = blockIdx.x*blockDim.x + threadIdx.x;
  float chA=0.f, chB=0.f, chS=0.f, cons=0.f, pen=0.f, lap=0.f;
  if (i < V){
    float inf = __int_as_float(0x7f800000);
    float mA = inf, mB = inf, mS = inf;
    #pragma unroll 4
    for (int c = 0; c < NCH; c++){
      mA = fminf(mA, g_part[(size_t)(0*NCH + c)*VCAP + i]);
      mB = fminf(mB, g_part[(size_t)(1*NCH + c)*VCAP + i]);
      mS = fminf(mS, g_part[(size_t)(2*NCH + c)*VCAP + i]);
    }
    F3 nv = newv(verts, deform, i);
    float qn = dot3(nv, nv);
    F3 tg = ld3(trg, i);
    float qt = dot3(tg, tg);
    chA = mA + qn;
    chB = mB + qt;
    chS = mS + qn;

    F3 a = ld3(g_vni, i);
    float ia = 1.0f / fmaxf(sqrtf(dot3(a,a)), 1e-6f);
    F3 ni; ni.x = a.x*ia; ni.y = a.y*ia; ni.z = a.z*ia;

    F3 b = ld3(g_vnn, i);
    float ib = 1.0f / fmaxf(sqrtf(dot3(b,b)), 1e-6f);
    float dx = b.x*ib - ni.x, dy = b.y*ib - ni.y, dz = b.z*ib - ni.z;
    cons = dx*dx + dy*dy + dz*dz;

    F3 df = ld3(deform, i);
    pen = fmaxf(-dot3(df, ni), 0.f);

    float r = g_rs[i];
    float inv = (r > 0.f) ? (1.0f / r) : 0.f;
    F3 lv = ld3(g_Lv, i);
    float ex = lv.x*inv - nv.x, ey = lv.y*inv - nv.y, ez = lv.z*inv - nv.z;
    lap = sqrtf(ex*ex + ey*ey + ez*ez);

    // restore zero-invariant for the next graph replay
    g_vni[3*i]=0.f; g_vni[3*i+1]=0.f; g_vni[3*i+2]=0.f;
    g_vnn[3*i]=0.f; g_vnn[3*i+1]=0.f; g_vnn[3*i+2]=0.f;
    g_Lv [3*i]=0.f; g_Lv [3*i+1]=0.f; g_Lv [3*i+2]=0.f;
    g_rs[i] = 0.f;
  }
  waccum(6, chA);
  waccum(7, chB);
  waccum(8, chS);
  waccum(4, cons);
  waccum(5, pen);
  waccum(3, lap);

  __syncthreads();
  if (threadIdx.x == 0){
    __threadfence();
    unsigned t = atomicAdd(&g_done, 1u);
    if (t == gridDim.x - 1){
      g_done = 0;
      double dV = (double)V, dF = (double)F, dE = (double)E;
      double loss = (g_acc[6] + g_acc[7]) / dV;      // chamfer
      loss += 0.1 * (g_acc[0] / dF);                 // edge
      loss += 0.1 * (g_acc[2] / dE);                 // normal consistency
      loss += 0.1 * (g_acc[1] / (3.0 * dF));         // smooth
      loss += 0.1 * (g_acc[3] / dV);                 // laplacian
      loss += 0.1 * (g_acc[4] / (3.0 * dV));         // consistency
      loss += 0.1 * (2.0 * g_acc[8] / dV);           // symmetry (2x rowmin)
      loss += 0.1 * (g_acc[5] / dV);                 // penetration
      out[0] = (float)loss;
      #pragma unroll
      for (int s = 0; s < 12; s++) g_acc[s] = 0.0;
    }
  }
}

extern "C" void kernel_launch(void* const* d_in, const int* in_sizes, int n_in,
                              void* d_out, int out_size){
  const float* verts  = (const float*)d_in[0];
  const float* deform = (const float*)d_in[1];
  const float* trg    = (const float*)d_in[2];
  const int*   faces  = (const int*)d_in[3];
  const int*   ev     = (const int*)d_in[4];
  const int*   eo     = (const int*)d_in[5];
  int V = in_sizes[0] / 3;
  int F = in_sizes[3] / 3;
  int E = in_sizes[4] / 2;
  int maxFE = F > E ? F : E;
  int FB = (maxFE + 255) / 256;
  int XB = (V + 2047) / 2048;
  int CH = (V + NCH - 1) / NCH;

  int blocks = FB + XB * 3 * NCH;
  k_main<<<blocks, 256>>>(verts, deform, trg, faces, ev, eo, V, F, E, FB, XB, CH);
  k_vert<<<(V + 255)/256, 256>>>(verts, deform, trg, (float*)d_out, V, F, E);
}